// round 2
// baseline (speedup 1.0000x reference)
#include <cuda_runtime.h>
#include <math.h>

// ---------------- scratch (no cudaMalloc allowed) ----------------
__device__ float g_x2[100352];        // ||x_i||^2, padded
__device__ float g_c2[2048];          // ||c_j||^2
__device__ float g_predsMM[2048];     // K_MM @ alpha
__device__ float g_preds_fallback[100352];
__device__ float g_partials[1024];    // block partial sums for loss

// ---------------- row squared-norm: one warp per row (D=128) ----------------
__global__ void rownorm_kernel(const float* __restrict__ A, float* __restrict__ o, int n) {
    int row  = blockIdx.x * 8 + (threadIdx.x >> 5);
    int lane = threadIdx.x & 31;
    if (row >= n) return;
    float4 v = ((const float4*)(A + (size_t)row * 128))[lane];
    float s = v.x*v.x + v.y*v.y + v.z*v.z + v.w*v.w;
    #pragma unroll
    for (int off = 16; off > 0; off >>= 1)
        s += __shfl_down_sync(0xffffffffu, s, off);
    if (lane == 0) o[row] = s;
}

// ---------------- fused RBF mat-vec: preds = exp(-(a2+b2-2 A@B^T)/(2s^2)) @ alpha ----
// BM=128, BN=128, BK=16; 256 threads; 8x8 microtile per thread.
__global__ void __launch_bounds__(256, 2)
rbf_mmv_kernel(const float* __restrict__ A,  const float* __restrict__ a2,
               const float* __restrict__ B,  const float* __restrict__ b2,
               const float* __restrict__ alpha,
               const float* __restrict__ sigma_p,
               float* __restrict__ preds, int nRows, int mCols)
{
    __shared__ float As[16][132];     // [k][m] transposed, 132 stride keeps 16B align
    __shared__ float Bs[16][132];
    __shared__ float sAlpha[128];
    __shared__ float sB2[128];
    __shared__ float sRed[128][17];

    const int tid = threadIdx.x;
    const int tx  = tid & 15;         // column group (8 cols)
    const int ty  = tid >> 4;         // row group    (8 rows)
    const int rowBase = blockIdx.x * 128;

    const float sg     = *sigma_p;
    const float inv2s2 = 1.0f / (2.0f * sg * sg);

    float myA2[8];
    #pragma unroll
    for (int r = 0; r < 8; ++r) {
        int row = rowBase + ty * 8 + r;
        myA2[r] = (row < nRows) ? a2[row] : 0.0f;
    }

    float predAcc[8];
    #pragma unroll
    for (int r = 0; r < 8; ++r) predAcc[r] = 0.0f;

    // tile loader mapping: 4 threads per row (float4 each), 64 rows/pass, 2 passes
    const int lm = tid >> 2;          // 0..63
    const int lq = tid & 3;           // 0..3

    for (int colBase = 0; colBase < mCols; colBase += 128) {
        if (tid < 128) {
            sAlpha[tid] = alpha[colBase + tid];
            sB2[tid]    = b2[colBase + tid];
        }

        float acc[8][8];
        #pragma unroll
        for (int r = 0; r < 8; ++r)
            #pragma unroll
            for (int c = 0; c < 8; ++c) acc[r][c] = 0.0f;

        for (int k0 = 0; k0 < 128; k0 += 16) {
            #pragma unroll
            for (int p = 0; p < 2; ++p) {
                int m   = lm + p * 64;
                int row = rowBase + m;
                float4 v = (row < nRows)
                    ? *(const float4*)(A + (size_t)row * 128 + k0 + lq * 4)
                    : make_float4(0.f, 0.f, 0.f, 0.f);
                As[lq*4+0][m] = v.x; As[lq*4+1][m] = v.y;
                As[lq*4+2][m] = v.z; As[lq*4+3][m] = v.w;

                int brow = colBase + m;
                float4 w = *(const float4*)(B + (size_t)brow * 128 + k0 + lq * 4);
                Bs[lq*4+0][m] = w.x; Bs[lq*4+1][m] = w.y;
                Bs[lq*4+2][m] = w.z; Bs[lq*4+3][m] = w.w;
            }
            __syncthreads();

            #pragma unroll
            for (int k = 0; k < 16; ++k) {
                float4 a0 = *(const float4*)&As[k][ty * 8];
                float4 a1 = *(const float4*)&As[k][ty * 8 + 4];
                float4 b0 = *(const float4*)&Bs[k][tx * 8];
                float4 b1 = *(const float4*)&Bs[k][tx * 8 + 4];
                float ar[8] = {a0.x, a0.y, a0.z, a0.w, a1.x, a1.y, a1.z, a1.w};
                float bc[8] = {b0.x, b0.y, b0.z, b0.w, b1.x, b1.y, b1.z, b1.w};
                #pragma unroll
                for (int r = 0; r < 8; ++r)
                    #pragma unroll
                    for (int c = 0; c < 8; ++c)
                        acc[r][c] = fmaf(ar[r], bc[c], acc[r][c]);
            }
            __syncthreads();
        }

        // fused epilogue: exp + weighted accumulate
        #pragma unroll
        for (int r = 0; r < 8; ++r) {
            float p = 0.0f;
            #pragma unroll
            for (int c = 0; c < 8; ++c) {
                float sq = myA2[r] + sB2[tx * 8 + c] - 2.0f * acc[r][c];
                p = fmaf(__expf(-sq * inv2s2), sAlpha[tx * 8 + c], p);
            }
            predAcc[r] += p;
        }
        __syncthreads();   // protect sAlpha/sB2 before next col tile overwrites
    }

    // reduce over the 16 column groups
    #pragma unroll
    for (int r = 0; r < 8; ++r) sRed[ty * 8 + r][tx] = predAcc[r];
    __syncthreads();
    if (tid < 128) {
        float s = 0.0f;
        #pragma unroll
        for (int j = 0; j < 16; ++j) s += sRed[tid][j];
        int row = rowBase + tid;
        if (row < nRows) preds[row] = s;
    }
}

// ---------------- loss partials: sum (preds - Y)^2, fixed-order ----------------
__global__ void sqerr_kernel(const float* __restrict__ preds, const float* __restrict__ Y,
                             float* __restrict__ partials, int n) {
    float s = 0.0f;
    for (int i = blockIdx.x * blockDim.x + threadIdx.x; i < n; i += gridDim.x * blockDim.x) {
        float d = preds[i] - Y[i];
        s = fmaf(d, d, s);
    }
    __shared__ float sm[256];
    sm[threadIdx.x] = s;
    __syncthreads();
    #pragma unroll
    for (int off = 128; off > 0; off >>= 1) {
        if (threadIdx.x < off) sm[threadIdx.x] += sm[threadIdx.x + off];
        __syncthreads();
    }
    if (threadIdx.x == 0) partials[blockIdx.x] = sm[0];
}

// ---------------- finalize: total = loss/N + exp(-penalty) * alpha^T (K_MM alpha) ----
__global__ void final_kernel(const float* __restrict__ partials, int nPart,
                             const float* __restrict__ alpha,
                             const float* __restrict__ predsMM, int m,
                             const float* __restrict__ penalty_p,
                             float* __restrict__ out_total, int n) {
    int tid = threadIdx.x;
    float s = 0.0f;
    for (int i = tid; i < nPart; i += 256) s += partials[i];
    float rg = 0.0f;
    for (int i = tid; i < m; i += 256) rg = fmaf(alpha[i], predsMM[i], rg);

    __shared__ float sm[256], sm2[256];
    sm[tid] = s; sm2[tid] = rg;
    __syncthreads();
    #pragma unroll
    for (int off = 128; off > 0; off >>= 1) {
        if (tid < off) { sm[tid] += sm[tid + off]; sm2[tid] += sm2[tid + off]; }
        __syncthreads();
    }
    if (tid == 0)
        out_total[0] = sm[0] / (float)n + expf(-penalty_p[0]) * sm2[0];
}

// ---------------- launch ----------------
extern "C" void kernel_launch(void* const* d_in, const int* in_sizes, int n_in,
                              void* d_out, int out_size) {
    const float* X       = (const float*)d_in[0];
    const float* Y       = (const float*)d_in[1];
    const float* centers = (const float*)d_in[2];
    const float* alpha   = (const float*)d_in[3];
    const float* sigma   = (const float*)d_in[4];
    const float* penalty = (const float*)d_in[5];
    float* out = (float*)d_out;

    const int N = in_sizes[0] / 128;
    const int M = in_sizes[2] / 128;

    float *x2, *c2, *predsMM, *partials, *preds_fb;
    cudaGetSymbolAddress((void**)&x2,       g_x2);
    cudaGetSymbolAddress((void**)&c2,       g_c2);
    cudaGetSymbolAddress((void**)&predsMM,  g_predsMM);
    cudaGetSymbolAddress((void**)&partials, g_partials);
    cudaGetSymbolAddress((void**)&preds_fb, g_preds_fallback);

    // output layout: [total, preds(N)] if out_size == N+1; fallbacks otherwise
    float* preds_ptr = preds_fb;
    float* total_ptr = out;
    if (out_size >= N + 1)      { total_ptr = out; preds_ptr = out + 1; }
    else if (out_size == N)     { preds_ptr = out; total_ptr = preds_fb; } // no scalar slot
    // else out_size==1: preds to scratch, total to out[0]

    rownorm_kernel<<<(N + 7) / 8, 256>>>(X, x2, N);
    rownorm_kernel<<<(M + 7) / 8, 256>>>(centers, c2, M);

    // preds = K_NM @ alpha
    rbf_mmv_kernel<<<(N + 127) / 128, 256>>>(X, x2, centers, c2, alpha, sigma,
                                             preds_ptr, N, M);
    // K_MM @ alpha
    rbf_mmv_kernel<<<(M + 127) / 128, 256>>>(centers, c2, centers, c2, alpha, sigma,
                                             predsMM, M, M);

    sqerr_kernel<<<256, 256>>>(preds_ptr, Y, partials, N);
    final_kernel<<<1, 256>>>(partials, 256, alpha, predsMM, M, penalty, total_ptr, N);
}

// round 4
// speedup vs baseline: 8.4848x; 8.4848x over previous
#include <cuda_runtime.h>
#include <cuda_bf16.h>
#include <cstdint>
#include <math.h>

// ===================== constants =====================
static constexpr int DIMK = 128;        // feature dim
static constexpr int NPAD = 100352;     // padded X rows (>= 782*128)

// smem byte offsets (dynamic smem)
static constexpr int TILE_STRIDE = 272;             // 136 bf16, 16B aligned, conflict-free ldmatrix
static constexpr int TILE_BYTES  = 128 * TILE_STRIDE; // 34816
static constexpr int SM_A    = 0;
static constexpr int SM_B0   = TILE_BYTES;           // 34816
static constexpr int SM_B1   = 2 * TILE_BYTES;       // 69632
static constexpr int SM_CA0  = 3 * TILE_BYTES;       // 104448 (128 float2 = 1KB)
static constexpr int SM_CA1  = SM_CA0 + 1024;        // 105472
static constexpr int SM_RED  = SM_CA1 + 1024;        // 106496 (128*2 float)
static constexpr int SMEM_TOTAL = SM_RED + 1024;     // 107520

// ===================== scratch (no cudaMalloc allowed) =====================
__device__ __nv_bfloat16 g_Xb[(size_t)NPAD * DIMK];
__device__ __nv_bfloat16 g_Cb[2048 * DIMK];
__device__ float  g_x2[NPAD];
__device__ float  g_c2[2048];
__device__ float2 g_c2a[2048];          // (||c||^2, alpha)
__device__ float  g_predsMM[2048];
__device__ float  g_partials[512];
__device__ float  g_preds_fallback[NPAD];

// ===================== PTX helpers (baseline ISA only) =====================
__device__ __forceinline__ uint32_t smem_u32(const void* p) {
    uint32_t a;
    asm("{ .reg .u64 t; cvta.to.shared.u64 t, %1; cvt.u32.u64 %0, t; }" : "=r"(a) : "l"(p));
    return a;
}
__device__ __forceinline__ void cpa16(uint32_t dst, const void* src) {
    asm volatile("cp.async.cg.shared.global [%0], [%1], 16;" :: "r"(dst), "l"(src));
}
#define CP_COMMIT() asm volatile("cp.async.commit_group;" ::: "memory")
#define CP_WAIT0()  asm volatile("cp.async.wait_group 0;"  ::: "memory")

__device__ __forceinline__ void ldmx4(uint32_t* r, uint32_t addr) {
    asm volatile("ldmatrix.sync.aligned.m8n8.x4.shared.b16 {%0,%1,%2,%3}, [%4];"
                 : "=r"(r[0]), "=r"(r[1]), "=r"(r[2]), "=r"(r[3]) : "r"(addr));
}
__device__ __forceinline__ void mma16816(float* c, const uint32_t* a, const uint32_t* b) {
    asm volatile("mma.sync.aligned.m16n8k16.row.col.f32.bf16.bf16.f32 "
                 "{%0,%1,%2,%3}, {%4,%5,%6,%7}, {%8,%9}, {%0,%1,%2,%3};"
                 : "+f"(c[0]), "+f"(c[1]), "+f"(c[2]), "+f"(c[3])
                 : "r"(a[0]), "r"(a[1]), "r"(a[2]), "r"(a[3]), "r"(b[0]), "r"(b[1]));
}
__device__ __forceinline__ float ex2f(float x) {
    float y; asm("ex2.approx.ftz.f32 %0, %1;" : "=f"(y) : "f"(x)); return y;
}

// ===================== convert + row norms (norms from ROUNDED bf16!) =====
__global__ void conv_kernel(const float* __restrict__ A,
                            __nv_bfloat16* __restrict__ Ab,
                            float* __restrict__ norm2,
                            int n, int npad,
                            const float* __restrict__ alpha,   // may be null
                            float2* __restrict__ c2a)          // may be null
{
    int row  = blockIdx.x * 8 + (threadIdx.x >> 5);
    int lane = threadIdx.x & 31;
    if (row >= npad) return;
    float4 v = make_float4(0.f, 0.f, 0.f, 0.f);
    if (row < n) v = ((const float4*)(A + (size_t)row * DIMK))[lane];
    __nv_bfloat162 p0 = __floats2bfloat162_rn(v.x, v.y);
    __nv_bfloat162 p1 = __floats2bfloat162_rn(v.z, v.w);
    float r0 = __bfloat162float(p0.x), r1 = __bfloat162float(p0.y);
    float r2 = __bfloat162float(p1.x), r3 = __bfloat162float(p1.y);
    float s = r0*r0 + r1*r1 + r2*r2 + r3*r3;
    #pragma unroll
    for (int o = 16; o > 0; o >>= 1) s += __shfl_xor_sync(0xffffffffu, s, o);
    __nv_bfloat162* dst = (__nv_bfloat162*)(Ab + (size_t)row * DIMK) + lane * 2;
    dst[0] = p0; dst[1] = p1;
    if (lane == 0) {
        norm2[row] = s;
        if (c2a) c2a[row] = make_float2(s, alpha[row]);
    }
}

// ===================== async tile loader: 128 rows x 256B -> padded smem ====
__device__ __forceinline__ void load_tile_async(uint32_t smBase,
                                                const __nv_bfloat16* __restrict__ src,
                                                int tid)
{
    #pragma unroll
    for (int it = 0; it < 8; ++it) {
        int i   = tid + it * 256;
        int row = i >> 4;
        int kb  = i & 15;
        cpa16(smBase + row * TILE_STRIDE + kb * 16,
              (const char*)src + row * 256 + kb * 16);
    }
}

// ===================== fused RBF matvec (HMMA mma.sync) =====================
// Blocks [0, nBlocksX): rows of X -> preds ; rest: rows of C -> predsMM
__global__ void __launch_bounds__(256, 2)
rbf_hmma_kernel(const __nv_bfloat16* __restrict__ Xb, const float* __restrict__ x2,
                const __nv_bfloat16* __restrict__ Cb, const float* __restrict__ c2,
                const float2* __restrict__ c2a,
                const float* __restrict__ sigma_p,
                float* __restrict__ preds, float* __restrict__ predsMM,
                int nRows, int nBlocksX, int mCols)
{
    extern __shared__ char smem[];
    const uint32_t sb = smem_u32(smem);
    const int tid   = threadIdx.x;
    const int lane  = tid & 31;
    const int wid   = tid >> 5;
    const int warpM = wid & 3;          // 4 warps over M (32 rows each)
    const int warpN = wid >> 2;         // 2 warps over N (64 cols each)
    const int g     = lane >> 2;        // groupID 0..7
    const int tq    = lane & 3;         // quad thread 0..3

    const bool isX = ((int)blockIdx.x < nBlocksX);
    const __nv_bfloat16* A = isX ? Xb : Cb;
    const float* a2v       = isX ? x2 : c2;
    float* outp            = isX ? preds : predsMM;
    const int rowBase      = (isX ? blockIdx.x : blockIdx.x - nBlocksX) * 128;
    const int outLimit     = isX ? nRows : mCols;

    const float sg      = *sigma_p;
    const float s2      = 1.44269504088896340736f / (2.f * sg * sg); // log2e/(2s^2)
    const float two_s2  = 2.f * s2;
    const float neg_s2  = -s2;

    // per-thread row constants: rows warpM*32 + mf*16 + g + h*8
    float ca[4];
    #pragma unroll
    for (int mf = 0; mf < 2; ++mf)
        #pragma unroll
        for (int h = 0; h < 2; ++h)
            ca[mf*2+h] = neg_s2 * a2v[rowBase + warpM*32 + mf*16 + g + h*8];

    // prologue: A tile + C tile 0 + CA slot 0
    load_tile_async(sb + SM_A,  A + (size_t)rowBase * DIMK, tid);
    load_tile_async(sb + SM_B0, Cb, tid);
    if (tid < 64) cpa16(sb + SM_CA0 + tid*16, (const char*)c2a + tid*16);
    CP_COMMIT();
    CP_WAIT0();
    __syncthreads();

    // ldmatrix per-lane base addresses
    const int ti = lane >> 3, rr = lane & 7;
    uint32_t aBase[2];
    #pragma unroll
    for (int mf = 0; mf < 2; ++mf) {
        int row = warpM*32 + mf*16 + (ti & 1)*8 + rr;
        aBase[mf] = sb + SM_A + row * TILE_STRIDE + (ti >> 1) * 16;
    }
    uint32_t bOff[4];  // without buffer base
    #pragma unroll
    for (int p = 0; p < 4; ++p) {
        int row = warpN*64 + p*16 + (ti >> 1)*8 + rr;
        bOff[p] = row * TILE_STRIDE + (ti & 1) * 16;
    }

    float rowAcc[4] = {0.f, 0.f, 0.f, 0.f};
    const int nT = mCols >> 7;   // 16

    for (int t = 0; t < nT; ++t) {
        const uint32_t sbB = (t & 1) ? SM_B1 : SM_B0;
        const uint32_t sCA = (t & 1) ? SM_CA1 : SM_CA0;
        // prefetch tile t+1 into the other buffer
        if (t + 1 < nT) {
            load_tile_async(sb + ((t & 1) ? SM_B0 : SM_B1),
                            Cb + (size_t)(t + 1) * 128 * DIMK, tid);
            if (tid < 64)
                cpa16(sb + ((t & 1) ? SM_CA0 : SM_CA1) + tid*16,
                      (const char*)(c2a + (size_t)(t + 1) * 128) + tid*16);
            CP_COMMIT();
        }

        float c[2][8][4];
        #pragma unroll
        for (int mf = 0; mf < 2; ++mf)
            #pragma unroll
            for (int nf = 0; nf < 8; ++nf)
                #pragma unroll
                for (int e = 0; e < 4; ++e) c[mf][nf][e] = 0.f;

        #pragma unroll
        for (int ks = 0; ks < 8; ++ks) {
            const uint32_t kOff = ks * 32;   // 16 bf16 = 32B
            uint32_t a[2][4];
            ldmx4(a[0], aBase[0] + kOff);
            ldmx4(a[1], aBase[1] + kOff);
            uint32_t b[8][2];
            #pragma unroll
            for (int p = 0; p < 4; ++p) {
                uint32_t r4[4];
                ldmx4(r4, sb + sbB + bOff[p] + kOff);
                b[2*p][0] = r4[0]; b[2*p][1] = r4[1];
                b[2*p+1][0] = r4[2]; b[2*p+1][1] = r4[3];
            }
            #pragma unroll
            for (int mf = 0; mf < 2; ++mf)
                #pragma unroll
                for (int nf = 0; nf < 8; ++nf)
                    mma16816(c[mf][nf], a[mf], b[nf]);
        }

        // fused epilogue: exp(-(a2+c2-2f)/(2s^2)) * alpha, accumulate per row
        const char* caP = smem + sCA + (size_t)warpN * 64 * 8;
        #pragma unroll
        for (int nf = 0; nf < 8; ++nf) {
            float4 cc = *(const float4*)(caP + (nf*8 + tq*2) * 8); // (c2_0,a_0,c2_1,a_1)
            #pragma unroll
            for (int mf = 0; mf < 2; ++mf) {
                float e0 = fmaf(two_s2, c[mf][nf][0], fmaf(neg_s2, cc.x, ca[mf*2]));
                float e1 = fmaf(two_s2, c[mf][nf][1], fmaf(neg_s2, cc.z, ca[mf*2]));
                float e2 = fmaf(two_s2, c[mf][nf][2], fmaf(neg_s2, cc.x, ca[mf*2+1]));
                float e3 = fmaf(two_s2, c[mf][nf][3], fmaf(neg_s2, cc.z, ca[mf*2+1]));
                rowAcc[mf*2]   = fmaf(ex2f(e0), cc.y, rowAcc[mf*2]);
                rowAcc[mf*2]   = fmaf(ex2f(e1), cc.w, rowAcc[mf*2]);
                rowAcc[mf*2+1] = fmaf(ex2f(e2), cc.y, rowAcc[mf*2+1]);
                rowAcc[mf*2+1] = fmaf(ex2f(e3), cc.w, rowAcc[mf*2+1]);
            }
        }

        CP_WAIT0();
        __syncthreads();
    }

    // reduce across the quad (4 threads share each row)
    #pragma unroll
    for (int i = 0; i < 4; ++i) {
        rowAcc[i] += __shfl_xor_sync(0xffffffffu, rowAcc[i], 1);
        rowAcc[i] += __shfl_xor_sync(0xffffffffu, rowAcc[i], 2);
    }
    float* red = (float*)(smem + SM_RED);
    if (tq == 0) {
        #pragma unroll
        for (int mf = 0; mf < 2; ++mf)
            #pragma unroll
            for (int h = 0; h < 2; ++h) {
                int row = warpM*32 + mf*16 + g + h*8;
                red[row * 2 + warpN] = rowAcc[mf*2 + h];
            }
    }
    __syncthreads();
    if (tid < 128) {
        int row = rowBase + tid;
        if (row < outLimit) outp[row] = red[tid*2] + red[tid*2 + 1];
    }
}

// ===================== loss partials =====================
__global__ void sqerr_kernel(const float* __restrict__ preds, const float* __restrict__ Y,
                             float* __restrict__ partials, int n) {
    float s = 0.0f;
    for (int i = blockIdx.x * blockDim.x + threadIdx.x; i < n; i += gridDim.x * blockDim.x) {
        float d = preds[i] - Y[i];
        s = fmaf(d, d, s);
    }
    __shared__ float sm[256];
    sm[threadIdx.x] = s;
    __syncthreads();
    #pragma unroll
    for (int off = 128; off > 0; off >>= 1) {
        if (threadIdx.x < off) sm[threadIdx.x] += sm[threadIdx.x + off];
        __syncthreads();
    }
    if (threadIdx.x == 0) partials[blockIdx.x] = sm[0];
}

// ===================== finalize =====================
__global__ void final_kernel(const float* __restrict__ partials, int nPart,
                             const float* __restrict__ alpha,
                             const float* __restrict__ predsMM, int m,
                             const float* __restrict__ penalty_p,
                             float* __restrict__ out_total, int n) {
    int tid = threadIdx.x;
    float s = 0.0f;
    for (int i = tid; i < nPart; i += 256) s += partials[i];
    float rg = 0.0f;
    for (int i = tid; i < m; i += 256) rg = fmaf(alpha[i], predsMM[i], rg);
    __shared__ float sm[256], sm2[256];
    sm[tid] = s; sm2[tid] = rg;
    __syncthreads();
    #pragma unroll
    for (int off = 128; off > 0; off >>= 1) {
        if (tid < off) { sm[tid] += sm[tid + off]; sm2[tid] += sm2[tid + off]; }
        __syncthreads();
    }
    if (tid == 0)
        out_total[0] = sm[0] / (float)n + expf(-penalty_p[0]) * sm2[0];
}

// ===================== launch =====================
extern "C" void kernel_launch(void* const* d_in, const int* in_sizes, int n_in,
                              void* d_out, int out_size) {
    const float* X       = (const float*)d_in[0];
    const float* Y       = (const float*)d_in[1];
    const float* centers = (const float*)d_in[2];
    const float* alpha   = (const float*)d_in[3];
    const float* sigma   = (const float*)d_in[4];
    const float* penalty = (const float*)d_in[5];
    float* out = (float*)d_out;

    const int N = in_sizes[0] / DIMK;
    const int M = in_sizes[2] / DIMK;

    __nv_bfloat16 *Xb, *Cb;
    float *x2, *c2, *predsMM, *partials, *preds_fb;
    float2* c2a;
    cudaGetSymbolAddress((void**)&Xb,       g_Xb);
    cudaGetSymbolAddress((void**)&Cb,       g_Cb);
    cudaGetSymbolAddress((void**)&x2,       g_x2);
    cudaGetSymbolAddress((void**)&c2,       g_c2);
    cudaGetSymbolAddress((void**)&c2a,      g_c2a);
    cudaGetSymbolAddress((void**)&predsMM,  g_predsMM);
    cudaGetSymbolAddress((void**)&partials, g_partials);
    cudaGetSymbolAddress((void**)&preds_fb, g_preds_fallback);

    float* preds_ptr = preds_fb;
    float* total_ptr = out;
    if (out_size >= N + 1)  { total_ptr = out; preds_ptr = out + 1; }
    else if (out_size == N) { preds_ptr = out; total_ptr = preds_fb; }

    const int nBlocksX = (N + 127) / 128;
    const int nBlocksM = (M + 127) / 128;
    const int nPadX    = nBlocksX * 128;

    cudaFuncSetAttribute(rbf_hmma_kernel,
                         cudaFuncAttributeMaxDynamicSharedMemorySize, SMEM_TOTAL);

    conv_kernel<<<(nPadX + 7) / 8, 256>>>(X, Xb, x2, N, nPadX, nullptr, nullptr);
    conv_kernel<<<(M + 7) / 8, 256>>>(centers, Cb, c2, M, M, alpha, c2a);

    rbf_hmma_kernel<<<nBlocksX + nBlocksM, 256, SMEM_TOTAL>>>(
        Xb, x2, Cb, c2, c2a, sigma, preds_ptr, predsMM, N, nBlocksX, M);

    sqerr_kernel<<<256, 256>>>(preds_ptr, Y, partials, N);
    final_kernel<<<1, 256>>>(partials, 256, alpha, predsMM, M, penalty, total_ptr, N);
}